// round 5
// baseline (speedup 1.0000x reference)
#include <cuda_runtime.h>

// RSA_layer: output = c[-1] only  =>  softmax needed only for row i=1023.
//   s[j,u] = sum_v fs[j,v] * ( w_hi[v,u] + x[v]*w_dot[u] )  (i-const terms cancel,
//                                                            q folded into weights)
//   out[u] = sum_j fs[j,u]*exp(s[j,u]) / sum_j exp(s[j,u])
// Logits O(1) => exp without max-subtraction (validated rel_err ~2e-7).
//
// fs[j,v] = state[v*1024 + j + 1] for j < 1023;  fs[1023,v] = x[v]
//
// R5: 64 blocks x 256 threads (2 warps/SMSP for latency hiding), JB=16/block,
// 8 j per thread, in-block half-combine, 64-deep finalize by ticket-last block.

#define UNITS 128
#define WIN   1024
#define NBLK  64
#define TPB   256
#define JB    16          // j-rows per block
#define JT    8           // j-rows per thread

typedef unsigned long long u64;

__device__ float2 g_zc[NBLK * UNITS];
__device__ unsigned int g_cnt = 0;

__device__ __forceinline__ u64 pack2(float lo, float hi) {
    u64 r;
    asm("mov.b64 %0, {%1, %2};" : "=l"(r) : "f"(lo), "f"(hi));
    return r;
}
__device__ __forceinline__ void unpack2(u64 p, float& lo, float& hi) {
    asm("mov.b64 {%0, %1}, %2;" : "=f"(lo), "=f"(hi) : "l"(p));
}
__device__ __forceinline__ u64 ffma2(u64 a, u64 b, u64 c) {
    u64 d;
    asm("fma.rn.f32x2 %0, %1, %2, %3;" : "=l"(d) : "l"(a), "l"(b), "l"(c));
    return d;
}

__global__ void __launch_bounds__(TPB)
rsa_fused(const float* __restrict__ x,
          const float* __restrict__ state,
          const float* __restrict__ w,
          float* __restrict__ out)
{
    __shared__ __align__(16) float fs_sh[UNITS][JB];   // [v][j], j contiguous (8KB)
    __shared__ float x_sh[UNITS];
    __shared__ float2 comb[UNITS];
    __shared__ unsigned int s_ticket;

    const int t    = threadIdx.x;
    const int u    = t & (UNITS - 1);     // output column
    const int half = t >> 7;              // 0 or 1: which 8-j group
    const int j0   = blockIdx.x * JB;

    if (t < UNITS) x_sh[t] = x[t];

    // fs tile: 128v x 16j = 2048 floats, 8 per thread, ~2 lines per warp-LDG.
    #pragma unroll
    for (int k = 0; k < 8; k++) {
        int i = t + k * TPB;
        int v = i >> 4, j = i & (JB - 1);
        int jj = j0 + j;
        fs_sh[v][j] = (jj < WIN - 1) ? state[v * WIN + jj + 1] : x[v];
    }

    // w column for u: 128 independent LDGs, ptxas pipelines load->fold->FFMA2.
    const float* __restrict__ wu = w + u;          // w_hi[v][u] = w[v*128+u]
    const float wd = w[2 * UNITS * UNITS + u];     // w_dot[u]
    float wr[UNITS];
    #pragma unroll
    for (int v = 0; v < UNITS; v++) wr[v] = wu[v * UNITS];

    __syncthreads();   // fs_sh / x_sh ready

    // Fold q into effective weights: weff[v] = w_hi[v][u] + x[v]*wd
    #pragma unroll
    for (int v = 0; v < UNITS; v++) wr[v] = fmaf(x_sh[v], wd, wr[v]);

    // GEMM for this thread's 8 j-rows (offset jbase), packed FFMA2.
    const int jbase = half * JT;                   // 0 or 8 (32B offset, 8B-aligned)
    u64 s01 = 0, s23 = 0, s45 = 0, s67 = 0;
    #pragma unroll
    for (int v = 0; v < UNITS; v++) {
        u64 w2 = pack2(wr[v], wr[v]);
        const u64* fp = (const u64*)&fs_sh[v][jbase];   // broadcast LDS
        s01 = ffma2(fp[0], w2, s01);
        s23 = ffma2(fp[1], w2, s23);
        s45 = ffma2(fp[2], w2, s45);
        s67 = ffma2(fp[3], w2, s67);
    }

    float s[JT];
    unpack2(s01, s[0], s[1]);
    unpack2(s23, s[2], s[3]);
    unpack2(s45, s[4], s[5]);
    unpack2(s67, s[6], s[7]);

    // Partial softmax sums (no max pass: |s| is O(1) by construction).
    float z = 0.0f, c = 0.0f;
    #pragma unroll
    for (int j = 0; j < JT; j++) {
        float e = __expf(s[j]);
        z += e;
        c = fmaf(e, fs_sh[u][jbase + j], c);       // fs[j][u]
    }

    // Combine the two halves, one partial per (block, u).
    if (half == 1) comb[u] = make_float2(z, c);
    __syncthreads();
    if (half == 0) {
        float2 p = comb[u];
        g_zc[blockIdx.x * UNITS + u] = make_float2(z + p.x, c + p.y);
    }

    // Ticket: last-arriving block finalizes.
    __threadfence();
    __syncthreads();
    if (t == 0) s_ticket = atomicAdd(&g_cnt, 1u);
    __syncthreads();

    if (s_ticket == NBLK - 1) {
        __threadfence();   // acquire side
        if (t < UNITS) {
            float Z = 0.0f, C = 0.0f;
            #pragma unroll 16
            for (int b = 0; b < NBLK; b++) {       // coalesced LDG.64, L2-resident
                float2 p = g_zc[b * UNITS + t];
                Z += p.x;
                C += p.y;
            }
            out[t] = C / Z;
        }
        if (t == 0) g_cnt = 0;                     // reset for next graph replay
    }
}

extern "C" void kernel_launch(void* const* d_in, const int* in_sizes, int n_in,
                              void* d_out, int out_size)
{
    const float* x     = (const float*)d_in[0];   // input_tensor (1,128)
    const float* state = (const float*)d_in[1];   // state (128,1024)
    const float* w     = (const float*)d_in[2];   // w (257,128)
    // d_in[3] = b — cancels inside the softmax, unused.

    rsa_fused<<<NBLK, TPB>>>(x, state, w, (float*)d_out);
}

// round 6
// speedup vs baseline: 1.1600x; 1.1600x over previous
#include <cuda_runtime.h>

// RSA_layer: output = c[-1] only  =>  softmax needed only for row i=1023.
//   s[j,u] = (fs @ w_hi)[j,u] + q[j]*w_dot[u],   q[j] = x . fs[j]
//   out[u] = sum_j fs[j,u]*exp(s[j,u]) / sum_j exp(s[j,u])
// Logits O(1) => exp without max-subtraction (validated rel_err ~2e-7).
// fs[j,v] = state[v*1024 + j + 1] for j < 1023;  fs[1023,v] = x[v]
//
// R6: fma-issue model says per-SMSP FFMA cycles were the binding constraint.
//  - grid 128 x 256: JT=4 j-rows/thread -> per-warp FFMA2 halves
//  - q computed once/block by shuffle, applied AFTER the GEMM -> no per-v
//    weff FMA in the inner loop (pure LDS + 2xFFMA2)
//  => ~1024 fma-cyc/SMSP vs 2560 in R5.

#define UNITS 128
#define WIN   1024
#define NBLK  128
#define TPB   256
#define JB    8           // j-rows per block
#define JT    4           // j-rows per thread

typedef unsigned long long u64;

__device__ float2 g_zc[NBLK * UNITS];
__device__ unsigned int g_cnt = 0;

__device__ __forceinline__ u64 pack2(float lo, float hi) {
    u64 r;
    asm("mov.b64 %0, {%1, %2};" : "=l"(r) : "f"(lo), "f"(hi));
    return r;
}
__device__ __forceinline__ void unpack2(u64 p, float& lo, float& hi) {
    asm("mov.b64 {%0, %1}, %2;" : "=f"(lo), "=f"(hi) : "l"(p));
}
__device__ __forceinline__ u64 ffma2(u64 a, u64 b, u64 c) {
    u64 d;
    asm("fma.rn.f32x2 %0, %1, %2, %3;" : "=l"(d) : "l"(a), "l"(b), "l"(c));
    return d;
}

__global__ void __launch_bounds__(TPB)
rsa_fused(const float* __restrict__ x,
          const float* __restrict__ state,
          const float* __restrict__ w,
          float* __restrict__ out)
{
    __shared__ __align__(16) float fs_sh[UNITS][JB];   // [v][j], j contiguous (4KB)
    __shared__ float x_sh[UNITS];
    __shared__ float q_sh[JB];
    __shared__ float2 comb[UNITS];
    __shared__ unsigned int s_ticket;

    const int t    = threadIdx.x;
    const int u    = t & (UNITS - 1);     // output column
    const int half = t >> 7;              // 0/1: j-group 0-3 or 4-7
    const int j0   = blockIdx.x * JB;

    if (t < UNITS) x_sh[t] = x[t];

    // fs tile: 128v x 8j = 1024 floats, 4 per thread.
    #pragma unroll
    for (int k = 0; k < 4; k++) {
        int i = t + k * TPB;
        int v = i >> 3, j = i & (JB - 1);
        int jj = j0 + j;
        fs_sh[v][j] = (jj < WIN - 1) ? state[v * WIN + jj + 1] : x[v];
    }

    // w_hi column for u hoisted: 128 independent LDGs (ptxas pipelines them
    // against the FFMA2 consumers below).
    const float* __restrict__ wu = w + u;          // w_hi[v][u] = w[v*128+u]
    const float wd = w[2 * UNITS * UNITS + u];     // w_dot[u]
    float wr[UNITS];
    #pragma unroll
    for (int v = 0; v < UNITS; v++) wr[v] = wu[v * UNITS];

    __syncthreads();   // fs_sh / x_sh ready

    // q[j] = fs[j].x : 8 warps, warp jw owns one j. Tiny.
    {
        const int warp = t >> 5, lane = t & 31;
        float p = fs_sh[lane][warp]      * x_sh[lane]
                + fs_sh[lane + 32][warp] * x_sh[lane + 32]
                + fs_sh[lane + 64][warp] * x_sh[lane + 64]
                + fs_sh[lane + 96][warp] * x_sh[lane + 96];
        #pragma unroll
        for (int o = 16; o; o >>= 1) p += __shfl_xor_sync(0xffffffffu, p, o);
        if (lane == 0) q_sh[warp] = p;
    }

    // GEMM: pure {broadcast LDS.128 + 2x FFMA2} inner loop.
    const int jbase = half * JT;                   // 0 or 4 (16B-aligned offset)
    u64 s01 = 0, s23 = 0;
    #pragma unroll
    for (int v = 0; v < UNITS; v++) {
        u64 w2 = pack2(wr[v], wr[v]);              // alu-pipe MOV
        const u64* fp = (const u64*)&fs_sh[v][jbase];
        s01 = ffma2(fp[0], w2, s01);
        s23 = ffma2(fp[1], w2, s23);
    }

    float s[JT];
    unpack2(s01, s[0], s[1]);
    unpack2(s23, s[2], s[3]);

    __syncthreads();   // q_sh visible to all warps

    // Apply q*wd, partial softmax sums (no max pass: |s| is O(1)).
    float z = 0.0f, c = 0.0f;
    #pragma unroll
    for (int j = 0; j < JT; j++) {
        float e = __expf(fmaf(q_sh[jbase + j], wd, s[j]));
        z += e;
        c = fmaf(e, fs_sh[u][jbase + j], c);       // fs[j][u]
    }

    // Combine halves -> one partial per (block, u).
    if (half == 1) comb[u] = make_float2(z, c);
    __syncthreads();
    if (half == 0) {
        float2 p = comb[u];
        g_zc[blockIdx.x * UNITS + u] = make_float2(z + p.x, c + p.y);
    }

    // Ticket: last-arriving block finalizes.
    __threadfence();
    __syncthreads();
    if (t == 0) s_ticket = atomicAdd(&g_cnt, 1u);
    __syncthreads();

    if (s_ticket == NBLK - 1) {
        __threadfence();   // acquire side
        if (t < UNITS) {
            float Z = 0.0f, C = 0.0f;
            #pragma unroll 32
            for (int b = 0; b < NBLK; b++) {       // coalesced LDG.64, L2-resident
                float2 p = g_zc[b * UNITS + t];
                Z += p.x;
                C += p.y;
            }
            out[t] = C / Z;
        }
        if (t == 0) g_cnt = 0;                     // reset for next graph replay
    }
}

extern "C" void kernel_launch(void* const* d_in, const int* in_sizes, int n_in,
                              void* d_out, int out_size)
{
    const float* x     = (const float*)d_in[0];   // input_tensor (1,128)
    const float* state = (const float*)d_in[1];   // state (128,1024)
    const float* w     = (const float*)d_in[2];   // w (257,128)
    // d_in[3] = b — cancels inside the softmax, unused.

    rsa_fused<<<NBLK, TPB>>>(x, state, w, (float*)d_out);
}

// round 7
// speedup vs baseline: 1.1629x; 1.0025x over previous
#include <cuda_runtime.h>

// RSA_layer: output = c[-1] only  =>  softmax needed only for row i=1023.
//   s[j,u] = (fs @ w_hi)[j,u] + q[j]*w_dot[u],   q[j] = x . fs[j]
//   out[u] = sum_j fs[j,u]*exp(s[j,u]) / sum_j exp(s[j,u])
// Logits O(1) => exp without max-subtraction (validated rel_err ~2e-7).
// fs[j,v] = state[v*1024 + j + 1] for j < 1023;  fs[1023,v] = x[v]
//
// R7: v-split. Thread (u, h) does partial GEMM over its 64-v half for ALL 8 j:
//  - w LDG wavefronts/block: 1024 -> 512 (no duplicate column loads)
//  - GEMM smem reads: LDS.128 pairs, 2048 -> 1024 requests/block
//  - halves combined through smem, then half-0 finishes softmax partials.

#define UNITS 128
#define WIN   1024
#define NBLK  128
#define TPB   256
#define JB    8           // j-rows per block (all 8 per thread)
#define VH    64          // v-range per half

typedef unsigned long long u64;

__device__ float2 g_zc[NBLK * UNITS];
__device__ unsigned int g_cnt = 0;

__device__ __forceinline__ u64 pack2(float lo, float hi) {
    u64 r;
    asm("mov.b64 %0, {%1, %2};" : "=l"(r) : "f"(lo), "f"(hi));
    return r;
}
__device__ __forceinline__ void unpack2(u64 p, float& lo, float& hi) {
    asm("mov.b64 {%0, %1}, %2;" : "=f"(lo), "=f"(hi) : "l"(p));
}
__device__ __forceinline__ u64 ffma2(u64 a, u64 b, u64 c) {
    u64 d;
    asm("fma.rn.f32x2 %0, %1, %2, %3;" : "=l"(d) : "l"(a), "l"(b), "l"(c));
    return d;
}

__global__ void __launch_bounds__(TPB)
rsa_fused(const float* __restrict__ x,
          const float* __restrict__ state,
          const float* __restrict__ w,
          float* __restrict__ out)
{
    __shared__ __align__(16) float fs_sh[UNITS][JB];   // [v][j], j contiguous (4KB)
    __shared__ float x_sh[UNITS];
    __shared__ float q_sh[JB];
    __shared__ __align__(16) float comb[UNITS][JB];    // half-1 partials (4KB)
    __shared__ unsigned int s_ticket;

    const int t  = threadIdx.x;
    const int u  = t & (UNITS - 1);       // output column
    const int h  = t >> 7;                // v-half: 0 -> v[0,64), 1 -> v[64,128)
    const int j0 = blockIdx.x * JB;

    if (t < UNITS) x_sh[t] = x[t];

    // fs tile: 128v x 8j = 1024 floats, 4 per thread.
    #pragma unroll
    for (int k = 0; k < 4; k++) {
        int i = t + k * TPB;
        int v = i >> 3, j = i & (JB - 1);
        int jj = j0 + j;
        fs_sh[v][j] = (jj < WIN - 1) ? state[v * WIN + jj + 1] : x[v];
    }

    // This thread's 64-v slice of w_hi column u: 64 independent LDGs,
    // distinct per (u,h) -> no redundant wavefronts.
    const float* __restrict__ wu = w + h * VH * UNITS + u;  // w_hi[h*64+i][u]
    const float wd = w[2 * UNITS * UNITS + u];              // w_dot[u]
    float wr[VH];
    #pragma unroll
    for (int i = 0; i < VH; i++) wr[i] = wu[i * UNITS];

    __syncthreads();   // fs_sh / x_sh ready

    // q[j] = fs[j].x : 8 warps, warp jw owns one j.
    {
        const int warp = t >> 5, lane = t & 31;
        float p = fs_sh[lane][warp]      * x_sh[lane]
                + fs_sh[lane + 32][warp] * x_sh[lane + 32]
                + fs_sh[lane + 64][warp] * x_sh[lane + 64]
                + fs_sh[lane + 96][warp] * x_sh[lane + 96];
        #pragma unroll
        for (int o = 16; o; o >>= 1) p += __shfl_xor_sync(0xffffffffu, p, o);
        if (lane == 0) q_sh[warp] = p;
    }

    // Partial GEMM over this half's v: {2x LDS.128 + 4x FFMA2} per v.
    u64 s01 = 0, s23 = 0, s45 = 0, s67 = 0;
    #pragma unroll
    for (int i = 0; i < VH; i++) {
        u64 w2 = pack2(wr[i], wr[i]);                 // alu-pipe
        const ulonglong2* fp = (const ulonglong2*)fs_sh[h * VH + i];
        ulonglong2 f = *fp;                           // broadcast LDS.128: j0..3
        s01 = ffma2(f.x, w2, s01);
        s23 = ffma2(f.y, w2, s23);
        ulonglong2 g = fp[1];                         // broadcast LDS.128: j4..7
        s45 = ffma2(g.x, w2, s45);
        s67 = ffma2(g.y, w2, s67);
    }

    float sp[JB];
    unpack2(s01, sp[0], sp[1]);
    unpack2(s23, sp[2], sp[3]);
    unpack2(s45, sp[4], sp[5]);
    unpack2(s67, sp[6], sp[7]);

    // Half-1 publishes its partials (2x STS.128).
    if (h == 1) {
        *(float4*)&comb[u][0] = make_float4(sp[0], sp[1], sp[2], sp[3]);
        *(float4*)&comb[u][4] = make_float4(sp[4], sp[5], sp[6], sp[7]);
    }
    __syncthreads();   // also publishes q_sh

    // Half-0 combines, applies q*wd, computes softmax partials.
    if (h == 0) {
        float z = 0.0f, c = 0.0f;
        #pragma unroll
        for (int j = 0; j < JB; j++) {
            float sj = sp[j] + comb[u][j];
            float e  = __expf(fmaf(q_sh[j], wd, sj));
            z += e;
            c = fmaf(e, fs_sh[u][j], c);              // fs[j][u]
        }
        g_zc[blockIdx.x * UNITS + u] = make_float2(z, c);
    }

    // Ticket: last-arriving block finalizes.
    __threadfence();
    __syncthreads();
    if (t == 0) s_ticket = atomicAdd(&g_cnt, 1u);
    __syncthreads();

    if (s_ticket == NBLK - 1) {
        __threadfence();   // acquire side
        if (t < UNITS) {
            float Z = 0.0f, C = 0.0f;
            #pragma unroll 32
            for (int b = 0; b < NBLK; b++) {          // coalesced LDG.64, L2-resident
                float2 p = g_zc[b * UNITS + t];
                Z += p.x;
                C += p.y;
            }
            out[t] = C / Z;
        }
        if (t == 0) g_cnt = 0;                        // reset for next graph replay
    }
}

extern "C" void kernel_launch(void* const* d_in, const int* in_sizes, int n_in,
                              void* d_out, int out_size)
{
    const float* x     = (const float*)d_in[0];   // input_tensor (1,128)
    const float* state = (const float*)d_in[1];   // state (128,1024)
    const float* w     = (const float*)d_in[2];   // w (257,128)
    // d_in[3] = b — cancels inside the softmax, unused.

    rsa_fused<<<NBLK, TPB>>>(x, state, w, (float*)d_out);
}